// round 1
// baseline (speedup 1.0000x reference)
#include <cuda_runtime.h>
#include <math.h>

#define DTs 0.2f
#define TILE 54         // output tile (per CTA)
#define HALO 5          // 5 convs after the degenerate first step
#define REGN 64         // smem region = TILE + 2*HALO
#define NTX 64
#define NTY 4
#define RPT 16          // rows per thread (REGN / NTY)

__global__ __launch_bounds__(NTX * NTY)
void vib_fused_kernel(const float* __restrict__ force,
                      const float* __restrict__ cw,     // [C,1,3,3]
                      const float* __restrict__ omega,  // [1,C,1,1]
                      const float* __restrict__ zeta,   // [1,C,1,1]
                      float* __restrict__ out,
                      int H, int W, int C)
{
    __shared__ float xs[REGN * REGN];

    const int tx = threadIdx.x;           // 0..63 : column within region
    const int ty = threadIdx.y;           // 0..3
    const int rb = ty * RPT;              // first owned row
    const int plane = blockIdx.z;         // b*C + c
    const int c = plane % C;
    const int gx0 = blockIdx.x * TILE - HALO;
    const int gy0 = blockIdx.y * TILE - HALO;

    // per-channel params
    const float o  = __ldg(omega + c);
    const float zt = __ldg(zeta + c);
    const float w  = logf(1.0f + expf(o));        // softplus
    const float z  = 1.0f / (1.0f + expf(-zt));   // sigmoid
    const float w2 = w * w;
    const float c1 = 1.0f - 2.0f * z * w * DTs;   // v damping factor
    const float cb = -w2;

    float k[9];
    #pragma unroll
    for (int i = 0; i < 9; i++) k[i] = __ldg(cw + c * 9 + i);

    const float* fp = force + (size_t)plane * H * W;

    // register state: force, velocity, own x-column
    float fr[RPT], vv[RPT], xc[RPT];

    const int gc = gx0 + tx;
    const bool cok = (gc >= 0) && (gc < W);

    // ---- Step 1 (x0 = v0 = 0 => conv term vanishes) ----
    #pragma unroll
    for (int i = 0; i < RPT; i++) {
        const int gr = gy0 + rb + i;
        float f = 0.0f;
        if (cok && gr >= 0 && gr < H) f = fp[(size_t)gr * W + gc];
        fr[i] = f;
        vv[i] = f * DTs;          // v1 = F*DT
        xc[i] = vv[i] * DTs;      // x1 = v1*DT  (0 outside image since f=0)
        xs[(rb + i) * REGN + tx] = xc[i];
    }
    __syncthreads();

    const bool cin = (tx >= 1) && (tx <= REGN - 2);

    // ---- Steps 2..6 : 5 conv+update iterations ----
    #pragma unroll 1
    for (int s = 0; s < 5; s++) {
        // pass 1: compute new v into registers (reads xs only)
        if (cin) {
            const int rtop = (rb - 1 < 0) ? 0 : rb - 1;
            float l0 = xs[rtop * REGN + tx - 1];
            float r0 = xs[rtop * REGN + tx + 1];
            float l1 = xs[rb   * REGN + tx - 1];
            float r1 = xs[rb   * REGN + tx + 1];
            const float cm      = xs[rtop * REGN + tx];
            const int   rbot    = (rb + RPT > REGN - 1) ? (REGN - 1) : (rb + RPT);
            const float cp_last = xs[rbot * REGN + tx];
            #pragma unroll
            for (int i = 0; i < RPT; i++) {
                const int r  = rb + i;
                const int rn = (r + 1 > REGN - 1) ? (REGN - 1) : (r + 1);
                const float l2 = xs[rn * REGN + tx - 1];
                const float r2 = xs[rn * REGN + tx + 1];
                const float ct  = (i == 0)       ? cm      : xc[i - 1];
                const float cbt = (i == RPT - 1) ? cp_last : xc[i + 1];
                if (r >= 1 && r <= REGN - 2) {
                    float inter = k[0] * l0 + k[1] * ct    + k[2] * r0
                                + k[3] * l1 + k[4] * xc[i] + k[5] * r1
                                + k[6] * l2 + k[7] * cbt   + k[8] * r2;
                    vv[i] = c1 * vv[i] + DTs * (cb * xc[i] + fr[i] + inter);
                }
                l0 = l1; l1 = l2; r0 = r1; r1 = r2;
            }
        }
        __syncthreads();
        // pass 2: x += v*DT (masked to 0 outside the true image => zero padding)
        if (cin) {
            #pragma unroll
            for (int i = 0; i < RPT; i++) {
                const int r = rb + i;
                if (r >= 1 && r <= REGN - 2) {
                    const int gr = gy0 + r;
                    const bool ok = cok && (gr >= 0) && (gr < H);
                    const float xn = ok ? (xc[i] + vv[i] * DTs) : 0.0f;
                    xc[i] = xn;
                    xs[r * REGN + tx] = xn;
                }
            }
        }
        __syncthreads();
    }

    // ---- Energy output on the valid 54x54 interior ----
    if (cok && tx >= HALO && tx <= REGN - 1 - HALO) {
        float* op = out + (size_t)plane * H * W;
        #pragma unroll
        for (int i = 0; i < RPT; i++) {
            const int r = rb + i;
            if (r >= HALO && r <= REGN - 1 - HALO) {
                const int gr = gy0 + r;
                if (gr >= 0 && gr < H) {
                    const float e = 0.5f * vv[i] * vv[i]
                                  + 0.5f * w2 * xc[i] * xc[i];
                    op[(size_t)gr * W + gc] = e;
                }
            }
        }
    }
}

extern "C" void kernel_launch(void* const* d_in, const int* in_sizes, int n_in,
                              void* d_out, int out_size)
{
    const float* force = (const float*)d_in[0];
    const float* cw    = (const float*)d_in[1];
    const float* omega = (const float*)d_in[2];
    const float* zeta  = (const float*)d_in[3];
    float* out = (float*)d_out;

    const int H = 256, W = 256;
    const int C = in_sizes[2];                 // omega has C elements
    const int planes = in_sizes[0] / (H * W);  // B*C

    dim3 block(NTX, NTY);
    dim3 grid((W + TILE - 1) / TILE, (H + TILE - 1) / TILE, planes);
    vib_fused_kernel<<<grid, block>>>(force, cw, omega, zeta, out, H, W, C);
}

// round 2
// speedup vs baseline: 1.0369x; 1.0369x over previous
#include <cuda_runtime.h>
#include <math.h>

typedef unsigned long long ull;

#define DTs  0.2f
#define TILE 54
#define HALO 5
#define REGN 64
#define NTX  32
#define NTY  8
#define RPT  8   // rows per thread

// ---- packed f32x2 helpers (Blackwell sm_103a) ----
__device__ __forceinline__ ull fma2(ull a, ull b, ull c) {
    ull d; asm("fma.rn.f32x2 %0, %1, %2, %3;" : "=l"(d) : "l"(a), "l"(b), "l"(c)); return d;
}
__device__ __forceinline__ ull mul2(ull a, ull b) {
    ull d; asm("mul.rn.f32x2 %0, %1, %2;" : "=l"(d) : "l"(a), "l"(b)); return d;
}
__device__ __forceinline__ ull pk(float lo, float hi) {
    ull r; asm("mov.b64 %0, {%1, %2};" : "=l"(r) : "f"(lo), "f"(hi)); return r;
}
__device__ __forceinline__ float2 up(ull v) {
    float2 t; asm("mov.b64 {%0, %1}, %2;" : "=f"(t.x), "=f"(t.y) : "l"(v)); return t;
}

__global__ __launch_bounds__(NTX * NTY, 2)
void vib_fused2(const float* __restrict__ force,
                const float* __restrict__ cw,
                const float* __restrict__ omega,
                const float* __restrict__ zeta,
                float* __restrict__ out,
                int H, int W, int C)
{
    // smem: guard(34) | xe 66x32 | xo 66x32 | fs 64x64 | guard(34)
    __shared__ __align__(16) float sm[34 + 66*32 + 66*32 + 64*64 + 34];
    float* xe = sm + 34;          // even cols, row r at (r+1)*32
    float* xo = xe + 66*32;       // odd  cols
    float* fs = xo + 66*32;       // F*DT, interleaved pairs (8B aligned)

    const int tx = threadIdx.x, ty = threadIdx.y;
    const int rb = ty * RPT;
    const int plane = blockIdx.z;
    const int c = plane % C;
    const int gx0 = blockIdx.x * TILE - HALO;
    const int gy0 = blockIdx.y * TILE - HALO;

    // per-channel params (pre-scaled by DT where possible)
    const float o  = __ldg(omega + c);
    const float zt = __ldg(zeta + c);
    const float w  = log1pf(expf(o));            // softplus
    const float z  = 1.0f / (1.0f + expf(-zt));  // sigmoid
    const float w2 = w * w;
    const float c1s = 1.0f - 2.0f * z * w * DTs;
    const ull c1p   = pk(c1s, c1s);
    const ull cbdtp = pk(-w2 * DTs, -w2 * DTs);
    const ull DTp   = pk(DTs, DTs);

    ull kp[9];
    #pragma unroll
    for (int j = 0; j < 9; j++) {
        float kv = __ldg(cw + c * 9 + j) * DTs;  // fold DT into taps
        kp[j] = pk(kv, kv);
    }

    const float* fp = force + (size_t)plane * (H * W);

    // ---- cooperative load: fs = F*DT ; x1 = F*DT^2 into xe/xo ----
    const int tid = ty * NTX + tx;
    #pragma unroll
    for (int j = 0; j < 16; j++) {
        int idx = tid + j * 256;        // 0..4095
        int r  = idx >> 6;
        int cl = idx & 63;
        int gr = gy0 + r, gc = gx0 + cl;
        float f = 0.0f;
        if ((unsigned)gr < (unsigned)H && (unsigned)gc < (unsigned)W)
            f = __ldg(fp + gr * W + gc);
        f *= DTs;                        // v1
        fs[r * 64 + cl] = f;
        float x1 = f * DTs;              // x1
        ((cl & 1) ? xo : xe)[(r + 1) * 32 + (cl >> 1)] = x1;
    }
    if (tid < 32) {                      // zero pad rows (-1 and 64)
        xe[tid] = 0.0f; xo[tid] = 0.0f;
        xe[65 * 32 + tid] = 0.0f; xo[65 * 32 + tid] = 0.0f;
    }
    __syncthreads();

    float* pe = &xe[(rb + 1) * 32 + tx];
    float* po = &xo[(rb + 1) * 32 + tx];
    const float* pf = &fs[rb * 64 + 2 * tx];

    // register state (packed column pairs)
    ull vv[RPT], xc[RPT];
    unsigned mrow = 0;
    #pragma unroll
    for (int i = 0; i < RPT; i++) {
        ull f2 = *reinterpret_cast<const ull*>(pf + i * 64);
        vv[i] = f2;                      // v1 = F*DT
        xc[i] = mul2(f2, DTp);           // x1 = v1*DT
        if ((unsigned)(gy0 + rb + i) < (unsigned)H) mrow |= (1u << i);
    }
    const int gc0 = gx0 + 2 * tx, gc1 = gc0 + 1;
    const ull cmp = pk((unsigned)gc0 < (unsigned)W ? 1.0f : 0.0f,
                       (unsigned)gc1 < (unsigned)W ? 1.0f : 0.0f);

    // ---- 5 conv+update steps, no bounds checks (guards + erosion) ----
    #pragma unroll 1
    for (int s = 0; s < 5; s++) {
        // pass 1: conv + v update (reads smem x, regs only written)
        float ce_t = pe[-32], co_t = po[-32];       // row rb-1 centers
        ull C_t = pk(ce_t, co_t);
        ull L_t = pk(po[-33], ce_t);
        ull R_t = pk(co_t, pe[-31]);
        float2 x0 = up(xc[0]);
        ull L_m = pk(po[-1], x0.x);
        ull R_m = pk(x0.y, pe[1]);
        #pragma unroll
        for (int i = 0; i < RPT; i++) {
            ull C_b; float2 xb;
            if (i < RPT - 1) { C_b = xc[i + 1]; xb = up(C_b); }
            else { xb.x = pe[256]; xb.y = po[256]; C_b = pk(xb.x, xb.y); }
            ull L_b = pk(po[i * 32 + 31], xb.x);    // row rb+i+1 left
            ull R_b = pk(xb.y, pe[i * 32 + 33]);    // row rb+i+1 right

            ull acc = *reinterpret_cast<const ull*>(pf + i * 64);  // F*DT
            acc = fma2(cbdtp, xc[i], acc);
            acc = fma2(kp[0], L_t, acc);
            acc = fma2(kp[1], C_t, acc);
            acc = fma2(kp[2], R_t, acc);
            acc = fma2(kp[3], L_m, acc);
            acc = fma2(kp[4], xc[i], acc);
            acc = fma2(kp[5], R_m, acc);
            acc = fma2(kp[6], L_b, acc);
            acc = fma2(kp[7], C_b, acc);
            acc = fma2(kp[8], R_b, acc);
            vv[i] = fma2(c1p, vv[i], acc);

            C_t = xc[i]; L_t = L_m; R_t = R_m; L_m = L_b; R_m = R_b;
        }
        __syncthreads();
        // pass 2: x += v*DT, masked to true image (zero padding), write smem
        #pragma unroll
        for (int i = 0; i < RPT; i++) {
            ull xn = fma2(vv[i], DTp, xc[i]);
            xn = mul2(xn, cmp);
            xc[i] = ((mrow >> i) & 1u) ? xn : 0ULL;
            float2 t = up(xc[i]);
            pe[i * 32] = t.x;
            po[i * 32] = t.y;
        }
        __syncthreads();
    }

    // ---- energy output on valid 54x54 interior ----
    float* op = out + (size_t)plane * (H * W);
    const ull hp   = pk(0.5f, 0.5f);
    const ull hw2p = pk(0.5f * w2, 0.5f * w2);
    const bool c0w = (2 * tx >= HALO) && (2 * tx <= REGN - 1 - HALO) &&
                     ((unsigned)gc0 < (unsigned)W);
    const bool c1w = (2 * tx + 1 >= HALO) && (2 * tx + 1 <= REGN - 1 - HALO) &&
                     ((unsigned)gc1 < (unsigned)W);
    #pragma unroll
    for (int i = 0; i < RPT; i++) {
        int r = rb + i;
        if (r < HALO || r > REGN - 1 - HALO) continue;
        int gr = gy0 + r;
        if ((unsigned)gr >= (unsigned)H) continue;
        ull e = mul2(mul2(vv[i], vv[i]), hp);
        e = fma2(hw2p, mul2(xc[i], xc[i]), e);
        float2 t = up(e);
        size_t base = (size_t)gr * W;
        if (c0w) op[base + gc0] = t.x;
        if (c1w) op[base + gc1] = t.y;
    }
}

extern "C" void kernel_launch(void* const* d_in, const int* in_sizes, int n_in,
                              void* d_out, int out_size)
{
    const float* force = (const float*)d_in[0];
    const float* cw    = (const float*)d_in[1];
    const float* omega = (const float*)d_in[2];
    const float* zeta  = (const float*)d_in[3];
    float* out = (float*)d_out;

    const int H = 256, W = 256;
    const int C = in_sizes[2];
    const int planes = in_sizes[0] / (H * W);

    dim3 block(NTX, NTY);
    dim3 grid((W + TILE - 1) / TILE, (H + TILE - 1) / TILE, planes);
    vib_fused2<<<grid, block>>>(force, cw, omega, zeta, out, H, W, C);
}

// round 3
// speedup vs baseline: 1.3521x; 1.3040x over previous
#include <cuda_runtime.h>
#include <math.h>

typedef unsigned long long ull;

#define DTs  0.2f
#define TILE 54
#define HALO 5
#define NTX  32
#define NTY  8
#define RPT  8

// ---- packed f32x2 helpers (sm_103a) ----
__device__ __forceinline__ ull fma2(ull a, ull b, ull c) {
    ull d; asm("fma.rn.f32x2 %0, %1, %2, %3;" : "=l"(d) : "l"(a), "l"(b), "l"(c)); return d;
}
__device__ __forceinline__ ull mul2(ull a, ull b) {
    ull d; asm("mul.rn.f32x2 %0, %1, %2;" : "=l"(d) : "l"(a), "l"(b)); return d;
}
__device__ __forceinline__ ull add2(ull a, ull b) {
    ull d; asm("add.rn.f32x2 %0, %1, %2;" : "=l"(d) : "l"(a), "l"(b)); return d;
}
__device__ __forceinline__ ull pk(float lo, float hi) {
    ull r; asm("mov.b64 %0, {%1, %2};" : "=l"(r) : "f"(lo), "f"(hi)); return r;
}
__device__ __forceinline__ float2 up(ull v) {
    float2 t; asm("mov.b64 {%0, %1}, %2;" : "=f"(t.x), "=f"(t.y) : "l"(v)); return t;
}

template<bool EDGE>
__global__ __launch_bounds__(NTX * NTY, 2)
void vib3(const float* __restrict__ force,
          const float* __restrict__ cw,
          const float* __restrict__ omega,
          const float* __restrict__ zeta,
          float* __restrict__ out,
          int H, int W, int C)
{
    // smem: double-buffered inter-warp boundary rows + force pairs
    __shared__ ull xb[2][18][32];   // 9.2 KB  (guard slots 0 and 17 = zero)
    __shared__ ull fs[64][32];      // 16 KB   F*DT pairs, own-thread access only

    const int tx = threadIdx.x;     // lane = column pair
    const int ty = threadIdx.y;     // warp  = 8-row band
    const int rb = ty * RPT;
    const int plane = blockIdx.z;
    const int c = plane % C;

    int bx, by;
    if (EDGE) {
        const int e = blockIdx.x;   // 16 edge tiles of the 5x5 grid
        if      (e < 5)  { bx = e;      by = 0; }
        else if (e < 10) { bx = e - 5;  by = 4; }
        else if (e < 13) { bx = 0;      by = e - 9; }
        else             { bx = 4;      by = e - 12; }
    } else {
        bx = blockIdx.x + 1; by = blockIdx.y + 1;   // interior 3x3
    }
    const int gx0 = bx * TILE - HALO;
    const int gy0 = by * TILE - HALO;

    // per-channel params
    const float o  = __ldg(omega + c);
    const float zt = __ldg(zeta + c);
    const float w  = log1pf(expf(o));
    const float z  = 1.0f / (1.0f + expf(-zt));
    const float w2 = w * w;
    const float c1s = 1.0f - 2.0f * z * w * DTs;
    const ull c1p   = pk(c1s, c1s);
    const ull cbdtp = pk(-w2 * DTs, -w2 * DTs);
    const ull DTp   = pk(DTs, DTs);

    ull kp[9];
    #pragma unroll
    for (int j = 0; j < 9; j++) {
        const float kv = __ldg(cw + c * 9 + j) * DTs;   // fold DT
        kp[j] = pk(kv, kv);
    }

    const float* fp = force + (size_t)plane * (H * W);
    const int gc0 = gx0 + 2 * tx;

    // register state: x,v column-pairs for 8 owned rows
    ull vv[RPT], xc[RPT];
    unsigned mrow = 0;
    ull cmp = 0;
    if (EDGE)
        cmp = pk((unsigned)gc0 < (unsigned)W ? 1.0f : 0.0f,
                 (unsigned)(gc0 + 1) < (unsigned)W ? 1.0f : 0.0f);

    // ---- init: step 1 analytic (x0=v0=0 => v1=F*DT, x1=v1*DT) ----
    #pragma unroll
    for (int i = 0; i < RPT; i++) {
        const int gr = gy0 + rb + i;
        float f0 = 0.0f, f1 = 0.0f;
        if (!EDGE) {
            f0 = __ldg(fp + gr * W + gc0);
            f1 = __ldg(fp + gr * W + gc0 + 1);
        } else {
            const bool rok = (unsigned)gr < (unsigned)H;
            if (rok) mrow |= (1u << i);
            if (rok && (unsigned)gc0 < (unsigned)W)       f0 = __ldg(fp + gr * W + gc0);
            if (rok && (unsigned)(gc0 + 1) < (unsigned)W) f1 = __ldg(fp + gr * W + gc0 + 1);
        }
        const ull F2 = pk(f0 * DTs, f1 * DTs);
        fs[rb + i][tx] = F2;
        vv[i] = F2;                 // v1 = F*DT
        xc[i] = mul2(F2, DTp);      // x1 = v1*DT
    }
    // publish boundary rows of buffer 0; zero guard slots of both buffers
    xb[0][2 * ty + 1][tx] = xc[0];
    xb[0][2 * ty + 2][tx] = xc[7];
    if (ty == 0) {
        xb[0][0][tx] = 0ULL; xb[0][17][tx] = 0ULL;
        xb[1][0][tx] = 0ULL; xb[1][17][tx] = 0ULL;
    }
    __syncthreads();

    // ---- 5 fused conv+update steps, 1 barrier each ----
    #pragma unroll
    for (int s = 0; s < 5; s++) {
        ull (*curb)[32] = xb[s & 1];
        ull (*nxtb)[32] = xb[(s & 1) ^ 1];

        // top line (row rb-1) from smem, its shifted pairs via shuffle
        const ull T = curb[2 * ty][tx];
        const float2 t2 = up(T);
        ull Lt = pk(__shfl_up_sync(0xffffffffu, t2.y, 1), t2.x);
        ull Rt = pk(t2.y, __shfl_down_sync(0xffffffffu, t2.x, 1));
        ull Ct = T;
        // middle line (row rb)
        const float2 m2 = up(xc[0]);
        ull Lm = pk(__shfl_up_sync(0xffffffffu, m2.y, 1), m2.x);
        ull Rm = pk(m2.y, __shfl_down_sync(0xffffffffu, m2.x, 1));
        const ull B = curb[2 * ty + 3][tx];     // row rb+8

        #pragma unroll
        for (int i = 0; i < RPT; i++) {
            const ull Cb = (i < RPT - 1) ? xc[i + 1] : B;
            const float2 b2 = up(Cb);
            const ull Lb = pk(__shfl_up_sync(0xffffffffu, b2.y, 1), b2.x);
            const ull Rb = pk(b2.y, __shfl_down_sync(0xffffffffu, b2.x, 1));

            // split accumulator: depth ~6 instead of 11
            ull acc0 = fma2(cbdtp, xc[i], fs[rb + i][tx]);
            acc0 = fma2(kp[0], Lt, acc0);
            acc0 = fma2(kp[1], Ct, acc0);
            acc0 = fma2(kp[2], Rt, acc0);
            acc0 = fma2(kp[3], Lm, acc0);
            acc0 = fma2(kp[4], xc[i], acc0);
            ull acc1 = mul2(kp[5], Rm);
            acc1 = fma2(kp[6], Lb, acc1);
            acc1 = fma2(kp[7], Cb, acc1);
            acc1 = fma2(kp[8], Rb, acc1);
            acc1 = fma2(c1p, vv[i], acc1);
            vv[i] = add2(acc0, acc1);

            ull xn = fma2(vv[i], DTp, xc[i]);
            if (EDGE) {
                xn = mul2(xn, cmp);
                if (!((mrow >> i) & 1u)) xn = 0ULL;
            }
            // roll window (Ct must take OLD xc[i])
            Lt = Lm; Ct = xc[i]; Rt = Rm; Lm = Lb; Rm = Rb;
            xc[i] = xn;
        }
        // publish new boundary rows
        nxtb[2 * ty + 1][tx] = xc[0];
        nxtb[2 * ty + 2][tx] = xc[7];
        __syncthreads();
    }

    // ---- energy on valid interior [5,58]^2 of the region ----
    float* op = out + (size_t)plane * (H * W);
    const float hw2 = 0.5f * w2;
    const bool c0ok = (2 * tx >= HALO) && (2 * tx <= 63 - HALO) &&
                      (!EDGE || (unsigned)gc0 < (unsigned)W);
    const bool c1ok = (2 * tx + 1 >= HALO) && (2 * tx + 1 <= 63 - HALO) &&
                      (!EDGE || (unsigned)(gc0 + 1) < (unsigned)W);
    #pragma unroll
    for (int i = 0; i < RPT; i++) {
        const int r = rb + i;
        if (r < HALO || r > 63 - HALO) continue;
        const int gr = gy0 + r;
        if (EDGE && (unsigned)gr >= (unsigned)H) continue;
        const float2 v2 = up(vv[i]);
        const float2 x2 = up(xc[i]);
        const size_t base = (size_t)gr * W;
        if (c0ok) op[base + gc0]     = 0.5f * v2.x * v2.x + hw2 * x2.x * x2.x;
        if (c1ok) op[base + gc0 + 1] = 0.5f * v2.y * v2.y + hw2 * x2.y * x2.y;
    }
}

extern "C" void kernel_launch(void* const* d_in, const int* in_sizes, int n_in,
                              void* d_out, int out_size)
{
    const float* force = (const float*)d_in[0];
    const float* cw    = (const float*)d_in[1];
    const float* omega = (const float*)d_in[2];
    const float* zeta  = (const float*)d_in[3];
    float* out = (float*)d_out;

    const int H = 256, W = 256;
    const int C = in_sizes[2];
    const int planes = in_sizes[0] / (H * W);

    dim3 block(NTX, NTY);
    // interior 3x3 tiles
    vib3<false><<<dim3(3, 3, planes), block>>>(force, cw, omega, zeta, out, H, W, C);
    // 16 edge tiles
    vib3<true><<<dim3(16, 1, planes), block>>>(force, cw, omega, zeta, out, H, W, C);
}

// round 4
// speedup vs baseline: 1.4299x; 1.0576x over previous
#include <cuda_runtime.h>
#include <math.h>

typedef unsigned long long ull;

#define DTs  0.2f
#define TILE 54
#define HALO 5
#define NTX  32
#define NTY  16
#define RPT  4

// ---- packed f32x2 helpers (sm_103a) ----
__device__ __forceinline__ ull fma2(ull a, ull b, ull c) {
    ull d; asm("fma.rn.f32x2 %0, %1, %2, %3;" : "=l"(d) : "l"(a), "l"(b), "l"(c)); return d;
}
__device__ __forceinline__ ull mul2(ull a, ull b) {
    ull d; asm("mul.rn.f32x2 %0, %1, %2;" : "=l"(d) : "l"(a), "l"(b)); return d;
}
__device__ __forceinline__ ull add2(ull a, ull b) {
    ull d; asm("add.rn.f32x2 %0, %1, %2;" : "=l"(d) : "l"(a), "l"(b)); return d;
}
__device__ __forceinline__ ull pk(float lo, float hi) {
    ull r; asm("mov.b64 %0, {%1, %2};" : "=l"(r) : "f"(lo), "f"(hi)); return r;
}
__device__ __forceinline__ float2 up(ull v) {
    float2 t; asm("mov.b64 {%0, %1}, %2;" : "=f"(t.x), "=f"(t.y) : "l"(v)); return t;
}

template<bool EDGE>
__global__ __launch_bounds__(NTX * NTY, 2)
void vib4(const float* __restrict__ force,
          const float* __restrict__ cw,
          const float* __restrict__ omega,
          const float* __restrict__ zeta,
          float* __restrict__ out,
          int H, int W, int C)
{
    // double-buffered inter-warp boundary rows (slots 0 and 33 = zero guards)
    __shared__ ull xb[2][34][32];   // 17.4 KB
    __shared__ ull fs[64][32];      // 16 KB : F*DT pairs (own-thread access)

    const int tx = threadIdx.x;     // lane = column pair
    const int ty = threadIdx.y;     // warp  = 4-row band
    const int rb = ty * RPT;
    const int plane = blockIdx.z;
    const int c = plane % C;

    int bx, by;
    if (EDGE) {
        const int e = blockIdx.x;   // 16 edge tiles of the 5x5 grid
        if      (e < 5)  { bx = e;      by = 0; }
        else if (e < 10) { bx = e - 5;  by = 4; }
        else if (e < 13) { bx = 0;      by = e - 9; }
        else             { bx = 4;      by = e - 12; }
    } else {
        bx = blockIdx.x + 1; by = blockIdx.y + 1;
    }
    const int gx0 = bx * TILE - HALO;
    const int gy0 = by * TILE - HALO;

    // per-channel params
    const float o  = __ldg(omega + c);
    const float zt = __ldg(zeta + c);
    const float w  = log1pf(expf(o));
    const float z  = 1.0f / (1.0f + expf(-zt));
    const float w2 = w * w;
    const float c1s = 1.0f - 2.0f * z * w * DTs;
    const ull c1p   = pk(c1s, c1s);
    const ull cbdtp = pk(-w2 * DTs, -w2 * DTs);
    const ull DTp   = pk(DTs, DTs);

    ull kp[9];
    #pragma unroll
    for (int j = 0; j < 9; j++) {
        const float kv = __ldg(cw + c * 9 + j) * DTs;
        kp[j] = pk(kv, kv);
    }

    const float* fp = force + (size_t)plane * (H * W);
    const int gc0 = gx0 + 2 * tx;

    ull vv[RPT], xc[RPT];
    unsigned mrow = 0;
    ull cmp = 0;
    if (EDGE)
        cmp = pk((unsigned)gc0 < (unsigned)W ? 1.0f : 0.0f,
                 (unsigned)(gc0 + 1) < (unsigned)W ? 1.0f : 0.0f);

    // ---- init: step 1 analytic (v1 = F*DT, x1 = v1*DT) ----
    #pragma unroll
    for (int i = 0; i < RPT; i++) {
        const int gr = gy0 + rb + i;
        float f0 = 0.0f, f1 = 0.0f;
        if (!EDGE) {
            f0 = __ldg(fp + gr * W + gc0);
            f1 = __ldg(fp + gr * W + gc0 + 1);
        } else {
            const bool rok = (unsigned)gr < (unsigned)H;
            if (rok) mrow |= (1u << i);
            if (rok && (unsigned)gc0 < (unsigned)W)       f0 = __ldg(fp + gr * W + gc0);
            if (rok && (unsigned)(gc0 + 1) < (unsigned)W) f1 = __ldg(fp + gr * W + gc0 + 1);
        }
        const ull F2 = pk(f0 * DTs, f1 * DTs);
        fs[rb + i][tx] = F2;
        vv[i] = F2;
        xc[i] = mul2(F2, DTp);
    }
    // publish boundary rows of buffer 0; zero guard slots of both buffers
    xb[0][2 * ty + 1][tx] = xc[0];
    xb[0][2 * ty + 2][tx] = xc[RPT - 1];
    if (ty == 0) {
        xb[0][0][tx] = 0ULL; xb[0][33][tx] = 0ULL;
        xb[1][0][tx] = 0ULL; xb[1][33][tx] = 0ULL;
    }
    __syncthreads();

    // ---- 5 fused conv+update steps, 1 barrier each ----
    #pragma unroll
    for (int s = 0; s < 5; s++) {
        ull (*curb)[32] = xb[s & 1];
        ull (*nxtb)[32] = xb[(s & 1) ^ 1];

        const ull T = curb[2 * ty][tx];                 // row rb-1
        const float2 t2 = up(T);
        ull Lt = pk(__shfl_up_sync(0xffffffffu, t2.y, 1), t2.x);
        ull Rt = pk(t2.y, __shfl_down_sync(0xffffffffu, t2.x, 1));
        ull Ct = T;
        const float2 m2 = up(xc[0]);
        ull Lm = pk(__shfl_up_sync(0xffffffffu, m2.y, 1), m2.x);
        ull Rm = pk(m2.y, __shfl_down_sync(0xffffffffu, m2.x, 1));
        const ull B = curb[2 * ty + 3][tx];             // row rb+RPT

        #pragma unroll
        for (int i = 0; i < RPT; i++) {
            const ull Cb = (i < RPT - 1) ? xc[i + 1] : B;
            const float2 b2 = up(Cb);
            const ull Lb = pk(__shfl_up_sync(0xffffffffu, b2.y, 1), b2.x);
            const ull Rb = pk(b2.y, __shfl_down_sync(0xffffffffu, b2.x, 1));

            ull acc0 = fma2(cbdtp, xc[i], fs[rb + i][tx]);
            acc0 = fma2(kp[0], Lt, acc0);
            acc0 = fma2(kp[1], Ct, acc0);
            acc0 = fma2(kp[2], Rt, acc0);
            acc0 = fma2(kp[3], Lm, acc0);
            acc0 = fma2(kp[4], xc[i], acc0);
            ull acc1 = mul2(kp[5], Rm);
            acc1 = fma2(kp[6], Lb, acc1);
            acc1 = fma2(kp[7], Cb, acc1);
            acc1 = fma2(kp[8], Rb, acc1);
            acc1 = fma2(c1p, vv[i], acc1);
            vv[i] = add2(acc0, acc1);

            ull xn = fma2(vv[i], DTp, xc[i]);
            if (EDGE) {
                xn = mul2(xn, cmp);
                if (!((mrow >> i) & 1u)) xn = 0ULL;
            }
            Lt = Lm; Ct = xc[i]; Rt = Rm; Lm = Lb; Rm = Rb;
            xc[i] = xn;
        }
        nxtb[2 * ty + 1][tx] = xc[0];
        nxtb[2 * ty + 2][tx] = xc[RPT - 1];
        __syncthreads();
    }

    // ---- energy on valid interior [5,58]^2 of the region ----
    float* op = out + (size_t)plane * (H * W);
    const float hw2 = 0.5f * w2;
    const bool c0ok = (2 * tx >= HALO) && (2 * tx <= 63 - HALO) &&
                      (!EDGE || (unsigned)gc0 < (unsigned)W);
    const bool c1ok = (2 * tx + 1 >= HALO) && (2 * tx + 1 <= 63 - HALO) &&
                      (!EDGE || (unsigned)(gc0 + 1) < (unsigned)W);
    #pragma unroll
    for (int i = 0; i < RPT; i++) {
        const int r = rb + i;
        if (r < HALO || r > 63 - HALO) continue;
        const int gr = gy0 + r;
        if (EDGE && (unsigned)gr >= (unsigned)H) continue;
        const float2 v2 = up(vv[i]);
        const float2 x2 = up(xc[i]);
        const size_t base = (size_t)gr * W;
        if (c0ok) op[base + gc0]     = 0.5f * v2.x * v2.x + hw2 * x2.x * x2.x;
        if (c1ok) op[base + gc0 + 1] = 0.5f * v2.y * v2.y + hw2 * x2.y * x2.y;
    }
}

extern "C" void kernel_launch(void* const* d_in, const int* in_sizes, int n_in,
                              void* d_out, int out_size)
{
    const float* force = (const float*)d_in[0];
    const float* cw    = (const float*)d_in[1];
    const float* omega = (const float*)d_in[2];
    const float* zeta  = (const float*)d_in[3];
    float* out = (float*)d_out;

    const int H = 256, W = 256;
    const int C = in_sizes[2];
    const int planes = in_sizes[0] / (H * W);

    dim3 block(NTX, NTY);
    vib4<false><<<dim3(3, 3, planes), block>>>(force, cw, omega, zeta, out, H, W, C);
    vib4<true><<<dim3(16, 1, planes), block>>>(force, cw, omega, zeta, out, H, W, C);
}

// round 5
// speedup vs baseline: 1.4514x; 1.0151x over previous
#include <cuda_runtime.h>
#include <math.h>

typedef unsigned long long ull;

#define DTs  0.2f
#define TILE 54
#define HALO 5
#define NTX  32
#define NTY  16
#define RPT  4

// ---- packed f32x2 helpers (sm_103a) ----
__device__ __forceinline__ ull fma2(ull a, ull b, ull c) {
    ull d; asm("fma.rn.f32x2 %0, %1, %2, %3;" : "=l"(d) : "l"(a), "l"(b), "l"(c)); return d;
}
__device__ __forceinline__ ull mul2(ull a, ull b) {
    ull d; asm("mul.rn.f32x2 %0, %1, %2;" : "=l"(d) : "l"(a), "l"(b)); return d;
}
__device__ __forceinline__ ull add2(ull a, ull b) {
    ull d; asm("add.rn.f32x2 %0, %1, %2;" : "=l"(d) : "l"(a), "l"(b)); return d;
}
__device__ __forceinline__ ull pk(float lo, float hi) {
    ull r; asm("mov.b64 %0, {%1, %2};" : "=l"(r) : "f"(lo), "f"(hi)); return r;
}
__device__ __forceinline__ float2 up(ull v) {
    float2 t; asm("mov.b64 {%0, %1}, %2;" : "=f"(t.x), "=f"(t.y) : "l"(v)); return t;
}

struct TrueT  { static constexpr bool value = true;  };
struct FalseT { static constexpr bool value = false; };

__global__ __launch_bounds__(NTX * NTY, 2)
void vib5(const float* __restrict__ force,
          const float* __restrict__ cw,
          const float* __restrict__ omega,
          const float* __restrict__ zeta,
          float* __restrict__ out,
          int H, int W, int C)
{
    __shared__ ull xb[2][34][32];   // double-buffered warp-boundary rows (+guards)
    __shared__ ull fs[64][32];      // F*DT pairs

    const int tx = threadIdx.x;
    const int ty = threadIdx.y;
    const int rb = ty * RPT;
    const int plane = blockIdx.z;
    const int c = plane % C;
    const int bx = blockIdx.x, by = blockIdx.y;
    const bool edge = (bx == 0) | (bx == 4) | (by == 0) | (by == 4);

    const int gx0 = bx * TILE - HALO;
    const int gy0 = by * TILE - HALO;

    // per-channel params
    const float o  = __ldg(omega + c);
    const float zt = __ldg(zeta + c);
    const float w  = log1pf(expf(o));
    const float z  = 1.0f / (1.0f + expf(-zt));
    const float w2 = w * w;
    const float c1s = 1.0f - 2.0f * z * w * DTs;
    const ull c1p   = pk(c1s, c1s);
    const ull cbdtp = pk(-w2 * DTs, -w2 * DTs);
    const ull DTp   = pk(DTs, DTs);

    ull kp[9];
    #pragma unroll
    for (int j = 0; j < 9; j++) {
        const float kv = __ldg(cw + c * 9 + j) * DTs;
        kp[j] = pk(kv, kv);
    }

    const float* fp = force + (size_t)plane * (H * W);
    const int gc0 = gx0 + 2 * tx;
    const float c0f = ((unsigned)gc0 < (unsigned)W) ? 1.0f : 0.0f;
    const float c1f = ((unsigned)(gc0 + 1) < (unsigned)W) ? 1.0f : 0.0f;

    ull vv[RPT], xc[RPT], msk[RPT];

    // ---- init: step 1 analytic (v1 = F*DT, x1 = v1*DT), masked loads ----
    #pragma unroll
    for (int i = 0; i < RPT; i++) {
        const int gr = gy0 + rb + i;
        const bool rok = (unsigned)gr < (unsigned)H;
        float f0 = 0.0f, f1 = 0.0f;
        if (rok && c0f != 0.0f) f0 = __ldg(fp + gr * W + gc0);
        if (rok && c1f != 0.0f) f1 = __ldg(fp + gr * W + gc0 + 1);
        const float rf = rok ? 1.0f : 0.0f;
        msk[i] = pk(c0f * rf, c1f * rf);
        const ull F2 = pk(f0 * DTs, f1 * DTs);
        fs[rb + i][tx] = F2;
        vv[i] = F2;
        xc[i] = mul2(F2, DTp);
    }
    xb[0][2 * ty + 1][tx] = xc[0];
    xb[0][2 * ty + 2][tx] = xc[RPT - 1];
    if (ty == 0) {
        xb[0][0][tx] = 0ULL; xb[0][33][tx] = 0ULL;
        xb[1][0][tx] = 0ULL; xb[1][33][tx] = 0ULL;
    }
    __syncthreads();

    // ---- mainloop: 5 fused conv+update steps, 1 barrier each ----
    auto mainloop = [&](auto MASKC) {
        constexpr bool MASK = decltype(MASKC)::value;
        #pragma unroll 1
        for (int s = 0; s < 5; s++) {
            ull (*curb)[32] = xb[s & 1];
            ull (*nxtb)[32] = xb[(s & 1) ^ 1];

            const ull T = curb[2 * ty][tx];        // row rb-1
            const ull B = curb[2 * ty + 3][tx];    // row rb+RPT
            const float2 t2 = up(T);
            ull Lt = pk(__shfl_up_sync(0xffffffffu, t2.y, 1), t2.x);
            ull Rt = pk(t2.y, __shfl_down_sync(0xffffffffu, t2.x, 1));
            ull Ct = T;
            const float2 m2 = up(xc[0]);
            ull Lm = pk(__shfl_up_sync(0xffffffffu, m2.y, 1), m2.x);
            ull Rm = pk(m2.y, __shfl_down_sync(0xffffffffu, m2.x, 1));

            // prefetch row-0's below line (line 1) and its F
            ull Cb = xc[1];
            float2 b2 = up(Cb);
            float sl = __shfl_up_sync(0xffffffffu, b2.y, 1);
            float sr = __shfl_down_sync(0xffffffffu, b2.x, 1);
            ull Fi = fs[rb][tx];

            #pragma unroll
            for (int i = 0; i < RPT; i++) {
                const ull Lb = pk(sl, b2.x);
                const ull Rb = pk(b2.y, sr);

                // prefetch next row's below-line + F (hide SHFL/LDS latency)
                ull Cb_n = 0; float2 b2n; float sln = 0.f, srn = 0.f; ull Fn = 0;
                if (i < RPT - 1) {
                    Cb_n = (i + 1 < RPT - 1) ? xc[i + 2] : B;
                    b2n = up(Cb_n);
                    sln = __shfl_up_sync(0xffffffffu, b2n.y, 1);
                    srn = __shfl_down_sync(0xffffffffu, b2n.x, 1);
                    Fn = fs[rb + i + 1][tx];
                }

                ull acc0 = fma2(cbdtp, xc[i], Fi);
                acc0 = fma2(kp[0], Lt, acc0);
                acc0 = fma2(kp[1], Ct, acc0);
                acc0 = fma2(kp[2], Rt, acc0);
                acc0 = fma2(kp[3], Lm, acc0);
                acc0 = fma2(kp[4], xc[i], acc0);
                ull acc1 = mul2(kp[5], Rm);
                acc1 = fma2(kp[6], Lb, acc1);
                acc1 = fma2(kp[7], Cb, acc1);
                acc1 = fma2(kp[8], Rb, acc1);
                acc1 = fma2(c1p, vv[i], acc1);
                vv[i] = add2(acc0, acc1);

                ull xn = fma2(vv[i], DTp, xc[i]);
                if (MASK) xn = mul2(xn, msk[i]);

                Lt = Lm; Ct = xc[i]; Rt = Rm; Lm = Lb; Rm = Rb;
                xc[i] = xn;
                Cb = Cb_n; b2 = b2n; sl = sln; sr = srn; Fi = Fn;
            }
            nxtb[2 * ty + 1][tx] = xc[0];
            nxtb[2 * ty + 2][tx] = xc[RPT - 1];
            __syncthreads();
        }
    };

    if (edge) mainloop(TrueT{});
    else      mainloop(FalseT{});

    // ---- energy on valid interior [5,58]^2 of the region ----
    float* op = out + (size_t)plane * (H * W);
    const float hw2 = 0.5f * w2;
    const bool c0ok = (2 * tx >= HALO) && (2 * tx <= 63 - HALO) && (c0f != 0.0f);
    const bool c1ok = (2 * tx + 1 >= HALO) && (2 * tx + 1 <= 63 - HALO) && (c1f != 0.0f);
    #pragma unroll
    for (int i = 0; i < RPT; i++) {
        const int r = rb + i;
        if (r < HALO || r > 63 - HALO) continue;
        const int gr = gy0 + r;
        if ((unsigned)gr >= (unsigned)H) continue;
        const float2 v2 = up(vv[i]);
        const float2 x2 = up(xc[i]);
        const size_t base = (size_t)gr * W;
        if (c0ok) op[base + gc0]     = 0.5f * v2.x * v2.x + hw2 * x2.x * x2.x;
        if (c1ok) op[base + gc0 + 1] = 0.5f * v2.y * v2.y + hw2 * x2.y * x2.y;
    }
}

extern "C" void kernel_launch(void* const* d_in, const int* in_sizes, int n_in,
                              void* d_out, int out_size)
{
    const float* force = (const float*)d_in[0];
    const float* cw    = (const float*)d_in[1];
    const float* omega = (const float*)d_in[2];
    const float* zeta  = (const float*)d_in[3];
    float* out = (float*)d_out;

    const int H = 256, W = 256;
    const int C = in_sizes[2];
    const int planes = in_sizes[0] / (H * W);

    dim3 block(NTX, NTY);
    vib5<<<dim3(5, 5, planes), block>>>(force, cw, omega, zeta, out, H, W, C);
}